// round 7
// baseline (speedup 1.0000x reference)
#include <cuda_runtime.h>
#include <cuda_fp16.h>
#include <math.h>
#include <stdint.h>

#define H 96
#define W 96
#define HW (H*W)          // 9216
#define CIN 256
#define B 2
#define KK 9
#define GK (CIN*KK)       // 2304
#define GM 256
#define GN HW

// ---------------- scratch (static device allocations) -------------------------
__device__ __half g_colhi[(size_t)B * GK * HW];     // im2col hi plane [b][r][p]
__device__ __half g_collo[(size_t)B * GK * HW];     // im2col lo plane
__device__ float g_om[(size_t)B * 27 * HW];
__device__ float g_om_part[8ull * B * 27 * HW];
__device__ float g_h[(size_t)B * CIN * HW];         // layer-1 output [b][c][p]
__device__ float g_xT[(size_t)B * HW * CIN];        // transposed input [b][p][c]
__device__ __half g_whi[(size_t)GM * GK];           // W hi [o][r]
__device__ __half g_wlo[(size_t)GM * GK];           // W lo

// ---------------- helpers ------------------------------------------------------
__device__ __forceinline__ uint32_t sm_u32(const void* p) {
    uint32_t a;
    asm("{ .reg .u64 t; cvta.to.shared.u64 t, %1; cvt.u32.u64 %0, t; }" : "=r"(a) : "l"(p));
    return a;
}
__device__ __forceinline__ void cpasync16(uint32_t dst, const void* src) {
    asm volatile("cp.async.cg.shared.global [%0], [%1], 16;" :: "r"(dst), "l"(src));
}
#define CP_COMMIT() asm volatile("cp.async.commit_group;" ::: "memory")
#define CP_WAIT2()  asm volatile("cp.async.wait_group 2;" ::: "memory")

#define LDSM_X4(r0, r1, r2, r3, addr) \
    asm volatile("ldmatrix.sync.aligned.m8n8.x4.shared.b16 {%0,%1,%2,%3}, [%4];" \
        : "=r"(r0), "=r"(r1), "=r"(r2), "=r"(r3) : "r"(addr))
#define LDSM_X4_T(r0, r1, r2, r3, addr) \
    asm volatile("ldmatrix.sync.aligned.m8n8.x4.trans.shared.b16 {%0,%1,%2,%3}, [%4];" \
        : "=r"(r0), "=r"(r1), "=r"(r2), "=r"(r3) : "r"(addr))

#define MMA_F16(d, a, bb) \
    asm volatile("mma.sync.aligned.m16n8k16.row.col.f32.f16.f16.f32 " \
        "{%0,%1,%2,%3}, {%4,%5,%6,%7}, {%8,%9}, {%0,%1,%2,%3};" \
        : "+f"((d)[0]), "+f"((d)[1]), "+f"((d)[2]), "+f"((d)[3]) \
        : "r"((a)[0]), "r"((a)[1]), "r"((a)[2]), "r"((a)[3]), \
          "r"((bb)[0]), "r"((bb)[1]))

// packed f32x2 helpers
__device__ __forceinline__ uint64_t pk2(float x, float y) {
    uint64_t r;
    asm("mov.b64 %0, {%1, %2};" : "=l"(r) : "f"(x), "f"(y));
    return r;
}
__device__ __forceinline__ void fma2(uint64_t& d, uint64_t a, uint64_t b) {
    asm("fma.rn.f32x2 %0, %1, %2, %3;" : "=l"(d) : "l"(a), "l"(b), "l"(d));
}
__device__ __forceinline__ void mul2(uint64_t& d, uint64_t a, uint64_t b) {
    asm("mul.rn.f32x2 %0, %1, %2;" : "=l"(d) : "l"(a), "l"(b));
}

// ---------------- transpose: [C][HW] -> [HW][C] per batch ---------------------
// grid (HW/32, CIN/32, B), block (32, 8)
__global__ void transpose_kernel(const float* __restrict__ in,
                                 float* __restrict__ outT) {
    __shared__ float t[32][33];
    int b = blockIdx.z;
    int p0 = blockIdx.x * 32, c0 = blockIdx.y * 32;
    const float* ib = in + (size_t)b * CIN * HW;
    float* ob = outT + (size_t)b * HW * CIN;
    int tx = threadIdx.x, ty = threadIdx.y;
#pragma unroll
    for (int j = 0; j < 4; j++)
        t[ty + 8 * j][tx] = ib[(size_t)(c0 + ty + 8 * j) * HW + p0 + tx];
    __syncthreads();
#pragma unroll
    for (int j = 0; j < 4; j++)
        ob[(size_t)(p0 + ty + 8 * j) * CIN + c0 + tx] = t[tx][ty + 8 * j];
}

// ---------------- offset conv (SMEM-tiled): grid (36,8,B), block 256 ----------
__global__ void offset_conv_kernel(const float* __restrict__ x,
                                   const float* __restrict__ w_off,
                                   float* __restrict__ om_part) {
    int b = blockIdx.z, chunk = blockIdx.y, tile = blockIdx.x;
    int h0 = (tile / 6) * 16, w0 = (tile % 6) * 16;
    int ty = threadIdx.x >> 4, tx = threadIdx.x & 15;

    float acc[27];
#pragma unroll
    for (int i = 0; i < 27; i++) acc[i] = 0.f;

    __shared__ float ws[243];
    __shared__ float xt[18 * 18];
    const float* xb = x + (size_t)b * CIN * HW;
    int c0 = chunk * 32;
    for (int c = c0; c < c0 + 32; c++) {
        __syncthreads();
        if (threadIdx.x < 243) {
            int oc = threadIdx.x / 9, k = threadIdx.x % 9;
            ws[threadIdx.x] = w_off[((size_t)oc * CIN + c) * 9 + k];
        }
        const float* xc = xb + (size_t)c * HW;
        for (int idx = threadIdx.x; idx < 324; idx += 256) {
            int yy = h0 - 1 + idx / 18, xx = w0 - 1 + idx % 18;
            xt[idx] = (yy >= 0 && yy < H && xx >= 0 && xx < W) ? xc[yy * W + xx] : 0.f;
        }
        __syncthreads();
        float xv[9];
#pragma unroll
        for (int k = 0; k < 9; k++)
            xv[k] = xt[(ty + k / 3) * 18 + tx + k % 3];
#pragma unroll
        for (int oc = 0; oc < 27; oc++)
#pragma unroll
            for (int k = 0; k < 9; k++)
                acc[oc] = fmaf(ws[oc * 9 + k], xv[k], acc[oc]);
    }
    int h = h0 + ty, w = w0 + tx;
    float* dst = om_part + ((size_t)chunk * B * 27 + (size_t)b * 27) * HW + h * W + w;
#pragma unroll
    for (int oc = 0; oc < 27; oc++) dst[(size_t)oc * HW] = acc[oc];
}

__global__ void reduce_om_kernel(const float* __restrict__ part,
                                 const float* __restrict__ b_off,
                                 float* __restrict__ om) {
    int i = blockIdx.x * 256 + threadIdx.x;
    const int N = B * 27 * HW;
    int oc = (i / HW) % 27;
    float s = b_off[oc];
#pragma unroll
    for (int j = 0; j < 8; j++) s += part[(size_t)j * N + i];
    om[i] = s;
}

// ---------------- deformable im2col (transposed x) -> fp16 hi/lo --------------
// xT: [b][p][c]. Thread owns pixel pair (pa, pa+1), 64 channels (cc block).
// grid (HW/512, 9*4, B), block 256
__global__ void sample_kernel(const float* __restrict__ xT,
                              const float* __restrict__ om,
                              __half* __restrict__ chi,
                              __half* __restrict__ clo) {
    int b = blockIdx.z;
    int k = blockIdx.y % KK;
    int cc = blockIdx.y / KK;
    int pa = blockIdx.x * 512 + 2 * threadIdx.x;

    const float* omb = om + (size_t)b * 27 * HW;
    float2 dy = *(const float2*)(omb + (size_t)(2 * k) * HW + pa);
    float2 dx = *(const float2*)(omb + (size_t)(2 * k + 1) * HW + pa);
    float2 mm = *(const float2*)(omb + (size_t)(18 + k) * HW + pa);

    const float* xb = xT + (size_t)b * HW * CIN + cc * 64;
    const float* row[8];     // 4 positions x 2 pixels
    uint64_t wgt[8];         // packed (w,w) per position per pixel

#pragma unroll
    for (int px = 0; px < 2; px++) {
        int p = pa + px;
        int h = p / W, w = p % W;
        float dyv = px ? dy.y : dy.x;
        float dxv = px ? dx.y : dx.x;
        float mv  = px ? mm.y : mm.x;
        mv = 1.f / (1.f + __expf(-mv));

        float ys = (float)(h + k / 3 - 1) + dyv;
        float xs = (float)(w + k % 3 - 1) + dxv;
        float y0f = floorf(ys), x0f = floorf(xs);
        int y0 = (int)y0f, x0 = (int)x0f;
        int y1 = y0 + 1, x1 = x0 + 1;
        float wy1 = ys - y0f, wx1 = xs - x0f;
        float wy0 = 1.f - wy1, wx0 = 1.f - wx1;

        bool vy0 = (y0 >= 0) & (y0 < H), vy1 = (y1 >= 0) & (y1 < H);
        bool vx0 = (x0 >= 0) & (x0 < W), vx1 = (x1 >= 0) & (x1 < W);
        int yc0 = min(max(y0, 0), H - 1), yc1 = min(max(y1, 0), H - 1);
        int xc0 = min(max(x0, 0), W - 1), xc1 = min(max(x1, 0), W - 1);

        float w00 = wy0 * wx0 * ((vy0 & vx0) ? mv : 0.f);
        float w01 = wy0 * wx1 * ((vy0 & vx1) ? mv : 0.f);
        float w10 = wy1 * wx0 * ((vy1 & vx0) ? mv : 0.f);
        float w11 = wy1 * wx1 * ((vy1 & vx1) ? mv : 0.f);

        row[px * 4 + 0] = xb + (size_t)(yc0 * W + xc0) * CIN;
        row[px * 4 + 1] = xb + (size_t)(yc0 * W + xc1) * CIN;
        row[px * 4 + 2] = xb + (size_t)(yc1 * W + xc0) * CIN;
        row[px * 4 + 3] = xb + (size_t)(yc1 * W + xc1) * CIN;
        wgt[px * 4 + 0] = pk2(w00, w00);
        wgt[px * 4 + 1] = pk2(w01, w01);
        wgt[px * 4 + 2] = pk2(w10, w10);
        wgt[px * 4 + 3] = pk2(w11, w11);
    }

    size_t rbase = ((size_t)b * GK + (size_t)(cc * 64) * KK + k) * HW + pa;
    __half* hdst = chi + rbase;
    __half* ldst = clo + rbase;

#pragma unroll 4
    for (int q = 0; q < 16; q++) {
        int c = q * 4;
        float4 va4, vb4;
        {
            float4 f0 = *(const float4*)(row[0] + c);
            float4 f1 = *(const float4*)(row[1] + c);
            float4 f2 = *(const float4*)(row[2] + c);
            float4 f3 = *(const float4*)(row[3] + c);
            uint64_t lo = pk2(f0.x, f0.y), hi = pk2(f0.z, f0.w);
            mul2(lo, lo, wgt[0]); mul2(hi, hi, wgt[0]);
            fma2(lo, pk2(f1.x, f1.y), wgt[1]); fma2(hi, pk2(f1.z, f1.w), wgt[1]);
            fma2(lo, pk2(f2.x, f2.y), wgt[2]); fma2(hi, pk2(f2.z, f2.w), wgt[2]);
            fma2(lo, pk2(f3.x, f3.y), wgt[3]); fma2(hi, pk2(f3.z, f3.w), wgt[3]);
            asm("mov.b64 {%0, %1}, %2;" : "=f"(va4.x), "=f"(va4.y) : "l"(lo));
            asm("mov.b64 {%0, %1}, %2;" : "=f"(va4.z), "=f"(va4.w) : "l"(hi));
        }
        {
            float4 f0 = *(const float4*)(row[4] + c);
            float4 f1 = *(const float4*)(row[5] + c);
            float4 f2 = *(const float4*)(row[6] + c);
            float4 f3 = *(const float4*)(row[7] + c);
            uint64_t lo = pk2(f0.x, f0.y), hi = pk2(f0.z, f0.w);
            mul2(lo, lo, wgt[4]); mul2(hi, hi, wgt[4]);
            fma2(lo, pk2(f1.x, f1.y), wgt[5]); fma2(hi, pk2(f1.z, f1.w), wgt[5]);
            fma2(lo, pk2(f2.x, f2.y), wgt[6]); fma2(hi, pk2(f2.z, f2.w), wgt[6]);
            fma2(lo, pk2(f3.x, f3.y), wgt[7]); fma2(hi, pk2(f3.z, f3.w), wgt[7]);
            asm("mov.b64 {%0, %1}, %2;" : "=f"(vb4.x), "=f"(vb4.y) : "l"(lo));
            asm("mov.b64 {%0, %1}, %2;" : "=f"(vb4.z), "=f"(vb4.w) : "l"(hi));
        }
        const float* pva = &va4.x;
        const float* pvb = &vb4.x;
#pragma unroll
        for (int j = 0; j < 4; j++) {
            float va = pva[j], vb = pvb[j];
            __half2 h2 = __floats2half2_rn(va, vb);
            float2 bk = __half22float2(h2);
            __half2 l2 = __floats2half2_rn(va - bk.x, vb - bk.y);
            size_t off = (size_t)(c + j) * (KK * HW);
            *(__half2*)(hdst + off) = h2;
            *(__half2*)(ldst + off) = l2;
        }
    }
}

// ---------------- weight split fp32 -> fp16 hi/lo -----------------------------
__global__ void wsplit_kernel(const float* __restrict__ w,
                              __half* __restrict__ whi,
                              __half* __restrict__ wlo) {
    int i = blockIdx.x * 256 + threadIdx.x;
    float v = w[i];
    __half hi = __float2half_rn(v);
    whi[i] = hi;
    wlo[i] = __float2half_rn(v - __half2float(hi));
}

// ---------------- fp16 split GEMM + ReLU --------------------------------------
// CTA tile M=256 (full GM), N=128 pixels, K-chunk 32, 3-stage pipeline.
// grid (GN/128, 1, B) = 144 CTAs = 1 wave. 8 warps, warp tile 64x64.
#define NCH (GK / 32)                 // 72
#define STG_AH 0                      // 256 rows x 64B = 16 KB
#define STG_AL 16384
#define STG_BH 32768                  // 32 rows x 256B = 8 KB
#define STG_BL 40960
#define STG_SIZE 49152
#define NSTAGE 3
#define SM_BYTES (NSTAGE * STG_SIZE)  // 144 KB

__device__ __forceinline__ void load_stage(uint32_t sb, int k0, int tid,
                                           const __half* Ah, const __half* Al,
                                           const __half* Bh, const __half* Bl) {
    {
        int row = tid;
        const __half* sh = Ah + (size_t)row * GK + k0;
        const __half* sl = Al + (size_t)row * GK + k0;
        uint32_t rbase = sb + (uint32_t)row * 64;
        uint32_t sw = (uint32_t)((row >> 1) & 3);
#pragma unroll
        for (int j = 0; j < 4; j++) {
            uint32_t d = rbase + (uint32_t)((j ^ sw) << 4);
            cpasync16(d + STG_AH, sh + j * 8);
            cpasync16(d + STG_AL, sl + j * 8);
        }
    }
    {
        int row = tid >> 3;
        int c0 = tid & 7;
        const __half* sh = Bh + (size_t)(k0 + row) * GN;
        const __half* sl = Bl + (size_t)(k0 + row) * GN;
        uint32_t rbase = sb + (uint32_t)row * 256;
        uint32_t sw = (uint32_t)(row & 7);
#pragma unroll
        for (int j = 0; j < 2; j++) {
            int c = c0 + j * 8;
            uint32_t d = rbase + (uint32_t)((c ^ sw) << 4);
            cpasync16(d + STG_BH, sh + c * 8);
            cpasync16(d + STG_BL, sl + c * 8);
        }
    }
}

__global__ __launch_bounds__(256, 1)
void gemm_f16s_kernel(const __half* __restrict__ whi,
                      const __half* __restrict__ wlo,
                      const __half* __restrict__ chi,
                      const __half* __restrict__ clo,
                      float* __restrict__ Cc) {
    extern __shared__ char smc[];
    uint32_t smb = sm_u32(smc);
    const int tid = threadIdx.x;
    const int lane = tid & 31;
    const int wrp = tid >> 5;
    const int b = blockIdx.z;
    const int p0 = blockIdx.x * 128;

    const __half* Ah = whi;
    const __half* Al = wlo;
    const __half* Bh = chi + (size_t)b * GK * GN + p0;
    const __half* Bl = clo + (size_t)b * GK * GN + p0;

#pragma unroll
    for (int s = 0; s < NSTAGE; s++) {
        load_stage(smb + s * STG_SIZE, s * 32, tid, Ah, Al, Bh, Bl);
        CP_COMMIT();
    }

    const int wm = (wrp >> 1) * 64;
    const int wn8 = (wrp & 1) * 8;
    const int t8 = lane >> 3, r8 = lane & 7;
    const int ar = lane >> 2, ac = lane & 3;

    float acc[4][8][4];
#pragma unroll
    for (int i = 0; i < 4; i++)
#pragma unroll
        for (int j = 0; j < 8; j++)
#pragma unroll
            for (int q = 0; q < 4; q++) acc[i][j][q] = 0.f;

    int stg = 0;
    for (int ch = 0; ch < NCH; ch++) {
        CP_WAIT2();
        __syncthreads();
        uint32_t sb = smb + (uint32_t)stg * STG_SIZE;

#pragma unroll
        for (int ks = 0; ks < 2; ks++) {
            uint32_t ah[4][4], al[4][4];
#pragma unroll
            for (int mf = 0; mf < 4; mf++) {
                int mrow = wm + mf * 16 + r8 + 8 * (t8 & 1);
                int chk = 2 * ks + (t8 >> 1);
                uint32_t off = (uint32_t)mrow * 64 +
                               (uint32_t)((chk ^ ((mrow >> 1) & 3)) << 4);
                LDSM_X4(ah[mf][0], ah[mf][1], ah[mf][2], ah[mf][3], sb + STG_AH + off);
                LDSM_X4(al[mf][0], al[mf][1], al[mf][2], al[mf][3], sb + STG_AL + off);
            }
#pragma unroll
            for (int np = 0; np < 4; np++) {
                uint32_t bh[4], bl[4];
                int krow = 16 * ks + r8 + 8 * (t8 & 1);
                int chkb = wn8 + np * 2 + (t8 >> 1);
                uint32_t off = (uint32_t)krow * 256 +
                               (uint32_t)((chkb ^ (krow & 7)) << 4);
                LDSM_X4_T(bh[0], bh[1], bh[2], bh[3], sb + STG_BH + off);
                LDSM_X4_T(bl[0], bl[1], bl[2], bl[3], sb + STG_BL + off);
#pragma unroll
                for (int mf = 0; mf < 4; mf++)
#pragma unroll
                    for (int s = 0; s < 2; s++) {
                        float* d = acc[mf][np * 2 + s];
                        MMA_F16(d, ah[mf], &bh[s * 2]);
                        MMA_F16(d, ah[mf], &bl[s * 2]);
                        MMA_F16(d, al[mf], &bh[s * 2]);
                    }
            }
        }
        __syncthreads();

        if (ch + NSTAGE < NCH)
            load_stage(smb + (uint32_t)stg * STG_SIZE, (ch + NSTAGE) * 32, tid,
                       Ah, Al, Bh, Bl);
        CP_COMMIT();
        stg = (stg + 1 == NSTAGE) ? 0 : stg + 1;
    }

    float* Cb = Cc + (size_t)b * GM * GN;
    const int pb = p0 + (wrp & 1) * 64;
#pragma unroll
    for (int mf = 0; mf < 4; mf++) {
#pragma unroll
        for (int nf = 0; nf < 8; nf++) {
            int o = wm + mf * 16 + ar;
            int p = pb + nf * 8 + 2 * ac;
            float2 v0, v1;
            v0.x = fmaxf(acc[mf][nf][0], 0.f);
            v0.y = fmaxf(acc[mf][nf][1], 0.f);
            v1.x = fmaxf(acc[mf][nf][2], 0.f);
            v1.y = fmaxf(acc[mf][nf][3], 0.f);
            *(float2*)(Cb + (size_t)o * GN + p) = v0;
            *(float2*)(Cb + (size_t)(o + 8) * GN + p) = v1;
        }
    }
}

// ---------------- host side ----------------------------------------------------
static void run_layer(const float* xin, const float* w_off, const float* b_off,
                      const float* wmain, float* outp, float* xT,
                      __half* chi, __half* clo, float* om, float* om_part,
                      __half* whi, __half* wlo) {
    dim3 gOff(36, 8, B);
    offset_conv_kernel<<<gOff, 256>>>(xin, w_off, om_part);
    dim3 gT(HW / 32, CIN / 32, B);
    transpose_kernel<<<gT, dim3(32, 8)>>>(xin, xT);
    reduce_om_kernel<<<(B * 27 * HW) / 256, 256>>>(om_part, b_off, om);
    wsplit_kernel<<<(GM * GK) / 256, 256>>>(wmain, whi, wlo);
    dim3 gSamp(HW / 512, KK * 4, B);
    sample_kernel<<<gSamp, 256>>>(xT, om, chi, clo);
    dim3 gGemm(GN / 128, 1, B);
    gemm_f16s_kernel<<<gGemm, 256, SM_BYTES>>>(whi, wlo, chi, clo, outp);
}

extern "C" void kernel_launch(void* const* d_in, const int* in_sizes, int n_in,
                              void* d_out, int out_size) {
    const float* x      = (const float*)d_in[0];
    const float* w_off0 = (const float*)d_in[1];
    const float* b_off0 = (const float*)d_in[2];
    const float* w0     = (const float*)d_in[3];
    const float* w_off1 = (const float*)d_in[4];
    const float* b_off1 = (const float*)d_in[5];
    const float* w1     = (const float*)d_in[6];
    float* out = (float*)d_out;

    static bool attr_set = false;
    if (!attr_set) {
        cudaFuncSetAttribute(gemm_f16s_kernel,
                             cudaFuncAttributeMaxDynamicSharedMemorySize, SM_BYTES);
        attr_set = true;
    }

    __half *chi, *clo, *whi, *wlo;
    float *om, *om_part, *hbuf, *xT;
    cudaGetSymbolAddress((void**)&chi,     g_colhi);
    cudaGetSymbolAddress((void**)&clo,     g_collo);
    cudaGetSymbolAddress((void**)&om,      g_om);
    cudaGetSymbolAddress((void**)&om_part, g_om_part);
    cudaGetSymbolAddress((void**)&hbuf,    g_h);
    cudaGetSymbolAddress((void**)&xT,      g_xT);
    cudaGetSymbolAddress((void**)&whi,     g_whi);
    cudaGetSymbolAddress((void**)&wlo,     g_wlo);

    run_layer(x,    w_off0, b_off0, w0, hbuf, xT, chi, clo, om, om_part, whi, wlo);
    run_layer(hbuf, w_off1, b_off1, w1, out,  xT, chi, clo, om, om_part, whi, wlo);
}